// round 4
// baseline (speedup 1.0000x reference)
#include <cuda_runtime.h>
#include <cuda_fp16.h>

#define NN 100000
#define NE 3200000
#define NG 64

// ---------------- persistent scratch ----------------
__device__ int g_e64, g_b64;
__device__ int g_src32[NE];
__device__ int g_dst32[NE];
__device__ int g_batch32[NN];
__device__ int g_count[NN];
__device__ int g_off[NN + 1];
__device__ int g_cursor[NN];
__device__ int g_adj[NE];
__device__ int g_bsum[128];
__device__ __align__(16) unsigned int g_h1h[NN * 8];     // h1 as half2 pairs (16 ch/node)
__device__ __align__(16) float g_as1[NN * 4];
__device__ __align__(16) float g_ad1[NN * 4];
__device__ __align__(16) unsigned short g_h2h[NN * 32];  // h2w as half (32 ch/node)
__device__ float g_as2[NN];
__device__ float g_ad2[NN];
__device__ float g_pool[NG * 32];
__device__ float g_cnt[NG];

__device__ __forceinline__ float lrelu(float x) { return x > 0.f ? x : 0.2f * x; }
__device__ __forceinline__ float mishf(float x) {
    float sp = log1pf(__expf(x));
    return x * tanhf(sp);
}

// ---------------- zero init + dtype detect ----------------
__global__ void zero_detect_kernel(const int* __restrict__ ei, const int* __restrict__ bt) {
    int i = blockIdx.x * 256 + threadIdx.x;
    if (i < NN) g_count[i] = 0;
    if (i < NG * 32) g_pool[i] = 0.f;
    if (i < NG) g_cnt[i] = 0.f;
    if (blockIdx.x == 0) {
        int t = threadIdx.x, lane = t & 31;
        if (t < 32) {
            int v = ei[2 * lane + 1];
            unsigned any = __ballot_sync(0xffffffffu, v != 0);
            if (lane == 0) g_e64 = (any == 0u) ? 1 : 0;
        } else if (t < 64) {
            int v = bt[99999 - 2 * lane];
            unsigned any = __ballot_sync(0xffffffffu, v != 0);
            if (lane == 0) g_b64 = (any == 0u) ? 1 : 0;
        }
    }
}

// ---------------- fused: convert edges (+hist) and batch (+counts) ----------------
__global__ void conv_kernel(const void* __restrict__ ep, const void* __restrict__ bp) {
    int e = blockIdx.x * 256 + threadIdx.x;
    int lane = threadIdx.x & 31;
    if (e < NE) {
        int s, d;
        if (g_e64) {
            const long long* p = (const long long*)ep;
            s = (int)p[e];
            d = (int)p[NE + e];
        } else {
            const int* p = (const int*)ep;
            s = p[e];
            d = p[NE + e];
        }
        g_src32[e] = s;
        g_dst32[e] = d;
        atomicAdd(&g_count[d], 1);
    }
    int gid = -1;
    if (e < NN) {
        gid = g_b64 ? (int)((const long long*)bp)[e] : ((const int*)bp)[e];
        g_batch32[e] = gid;
    }
    unsigned mask = __match_any_sync(0xffffffffu, gid);
    if (gid >= 0 && (int)(__ffs(mask) - 1) == lane)
        atomicAdd(&g_cnt[gid], (float)__popc(mask));
}

// ---------------- scan (3 kernels) ----------------
__global__ void scan_a_kernel() {
    __shared__ int s[1024];
    int t = threadIdx.x;
    int i = blockIdx.x * 1024 + t;
    int c = (i < NN) ? g_count[i] : 0;
    s[t] = c;
    __syncthreads();
    for (int d = 1; d < 1024; d <<= 1) {
        int v = (t >= d) ? s[t - d] : 0;
        __syncthreads();
        s[t] += v;
        __syncthreads();
    }
    if (i < NN) g_off[i] = s[t];
    if (t == 1023) g_bsum[blockIdx.x] = s[1023];
}
__global__ void scan_b_kernel() {
    __shared__ int s[128];
    int t = threadIdx.x;
    int nb = (NN + 1023) / 1024;
    int v = (t < nb) ? g_bsum[t] : 0;
    s[t] = v;
    __syncthreads();
    for (int d = 1; d < 128; d <<= 1) {
        int u = (t >= d) ? s[t - d] : 0;
        __syncthreads();
        s[t] += u;
        __syncthreads();
    }
    g_bsum[t] = s[t];
}
__global__ void scan_c_kernel() {
    int i = blockIdx.x * 256 + threadIdx.x;
    if (i < NN) {
        int blk = i >> 10;
        int add = blk ? g_bsum[blk - 1] : 0;
        int ex = g_off[i] - g_count[i] + add;
        g_off[i] = ex;
        g_cursor[i] = ex;
    }
    if (i == 0) g_off[NN] = NE;
}

// ---------------- scatter: build CSR adjacency ----------------
__global__ void scatter_kernel() {
    int e = blockIdx.x * 256 + threadIdx.x;
    if (e >= NE) return;
    int d = g_dst32[e];
    int pos = atomicAdd(&g_cursor[d], 1);
    g_adj[pos] = g_src32[e];
}

// ---------------- GEMM1: h1 = x @ W1 (half out); per-(node,head) fp32 logits ------
// 128 threads, 64 nodes/block. Thread tile: 4 nodes x 2 cols (6 LDS.128 / 32 FMA).
#define G1N 64
__global__ void gemm1_kernel(const float* __restrict__ x, const float* __restrict__ W1,
                             const float* __restrict__ a_src1, const float* __restrict__ a_dst1) {
    __shared__ float xs[G1N * 132];   // 64 rows x 33 float4
    __shared__ float WsT[16 * 132];   // transposed W1
    int t = threadIdx.x;
    for (int i = t; i < 2048; i += 128) {
        int j = i >> 7, k = i & 127;
        WsT[j * 132 + k] = W1[k * 16 + j];
    }
    int nb = blockIdx.x * G1N;
    for (int i = t; i < G1N * 32; i += 128) {
        int row = i >> 5, c4 = i & 31;
        int n = nb + row;
        float4 v = make_float4(0.f, 0.f, 0.f, 0.f);
        if (n < NN) v = reinterpret_cast<const float4*>(x)[(size_t)n * 32 + c4];
        reinterpret_cast<float4*>(xs + row * 132)[c4] = v;
    }
    __syncthreads();

    int jp = t & 7;    // col pair: cols 2jp, 2jp+1
    int grp = t >> 3;  // rows 4*grp .. 4*grp+3
    const float4* wa = reinterpret_cast<const float4*>(WsT + (2 * jp) * 132);
    const float4* wb = reinterpret_cast<const float4*>(WsT + (2 * jp + 1) * 132);
    const float4* xr0 = reinterpret_cast<const float4*>(xs + (4 * grp + 0) * 132);
    const float4* xr1 = reinterpret_cast<const float4*>(xs + (4 * grp + 1) * 132);
    const float4* xr2 = reinterpret_cast<const float4*>(xs + (4 * grp + 2) * 132);
    const float4* xr3 = reinterpret_cast<const float4*>(xs + (4 * grp + 3) * 132);
    float a00 = 0.f, a01 = 0.f, a10 = 0.f, a11 = 0.f;
    float a20 = 0.f, a21 = 0.f, a30 = 0.f, a31 = 0.f;
#pragma unroll
    for (int k4 = 0; k4 < 32; k4++) {
        float4 w0 = wa[k4];
        float4 w1v = wb[k4];
        float4 v0 = xr0[k4];
        a00 = fmaf(v0.x, w0.x, a00); a00 = fmaf(v0.y, w0.y, a00);
        a00 = fmaf(v0.z, w0.z, a00); a00 = fmaf(v0.w, w0.w, a00);
        a01 = fmaf(v0.x, w1v.x, a01); a01 = fmaf(v0.y, w1v.y, a01);
        a01 = fmaf(v0.z, w1v.z, a01); a01 = fmaf(v0.w, w1v.w, a01);
        float4 v1 = xr1[k4];
        a10 = fmaf(v1.x, w0.x, a10); a10 = fmaf(v1.y, w0.y, a10);
        a10 = fmaf(v1.z, w0.z, a10); a10 = fmaf(v1.w, w0.w, a10);
        a11 = fmaf(v1.x, w1v.x, a11); a11 = fmaf(v1.y, w1v.y, a11);
        a11 = fmaf(v1.z, w1v.z, a11); a11 = fmaf(v1.w, w1v.w, a11);
        float4 v2 = xr2[k4];
        a20 = fmaf(v2.x, w0.x, a20); a20 = fmaf(v2.y, w0.y, a20);
        a20 = fmaf(v2.z, w0.z, a20); a20 = fmaf(v2.w, w0.w, a20);
        a21 = fmaf(v2.x, w1v.x, a21); a21 = fmaf(v2.y, w1v.y, a21);
        a21 = fmaf(v2.z, w1v.z, a21); a21 = fmaf(v2.w, w1v.w, a21);
        float4 v3 = xr3[k4];
        a30 = fmaf(v3.x, w0.x, a30); a30 = fmaf(v3.y, w0.y, a30);
        a30 = fmaf(v3.z, w0.z, a30); a30 = fmaf(v3.w, w0.w, a30);
        a31 = fmaf(v3.x, w1v.x, a31); a31 = fmaf(v3.y, w1v.y, a31);
        a31 = fmaf(v3.z, w1v.z, a31); a31 = fmaf(v3.w, w1v.w, a31);
    }
    float s0 = a_src1[2 * jp], s1 = a_src1[2 * jp + 1];
    float d0 = a_dst1[2 * jp], d1 = a_dst1[2 * jp + 1];
    float accA[4] = {a00, a10, a20, a30};
    float accB[4] = {a01, a11, a21, a31};
#pragma unroll
    for (int i = 0; i < 4; i++) {
        int n = nb + 4 * grp + i;
        float pa = accA[i], pb = accB[i];
        float ss = pa * s0 + pb * s1;
        float dd = pa * d0 + pb * d1;
        // pair-reduce across jp^1 (adjacent lane)
        ss += __shfl_xor_sync(0xffffffffu, ss, 1);
        dd += __shfl_xor_sync(0xffffffffu, dd, 1);
        if (n < NN) {
            __half2 hv = __floats2half2_rn(pa, pb);
            g_h1h[n * 8 + jp] = *reinterpret_cast<unsigned int*>(&hv);
            if ((jp & 1) == 0) {
                int h = jp >> 1;
                g_as1[n * 4 + h] = ss;
                g_ad1[n * 4 + h] = dd;
            }
        }
    }
}

// ---------------- Layer 1: warp/node, 8 groups x 4 lanes, half gathers ------------
__global__ void l1_edge_kernel(const float* __restrict__ b1, const float* __restrict__ W2,
                               const float* __restrict__ a_src2, const float* __restrict__ a_dst2) {
    __shared__ float W2s[512];
    int tid = threadIdx.x;
    for (int i = tid; i < 512; i += 256) W2s[i] = W2[i];
    __syncthreads();
    int lane = tid & 31;
    int n = blockIdx.x * 8 + (tid >> 5);
    int g = lane >> 2, r = lane & 3;
    float adv = g_ad1[n * 4 + r];
    int start = g_off[n], end = g_off[n + 1];
    const uint2* hp = reinterpret_cast<const uint2*>(g_h1h);

    float den, a0, a1, a2, a3;
    if (g == 0) {  // self loop
        float p = __expf(lrelu(g_as1[n * 4 + r] + adv));
        uint2 hv = hp[n * 4 + r];
        float2 f01 = __half22float2(*reinterpret_cast<__half2*>(&hv.x));
        float2 f23 = __half22float2(*reinterpret_cast<__half2*>(&hv.y));
        den = p;
        a0 = p * f01.x; a1 = p * f01.y; a2 = p * f23.x; a3 = p * f23.y;
    } else {
        den = 0.f; a0 = a1 = a2 = a3 = 0.f;
    }
    int idx = start + g;
    int src = (idx < end) ? g_adj[idx] : -1;
    while (src >= 0) {
        idx += 8;
        int nsrc = (idx < end) ? g_adj[idx] : -1;  // prefetch next index
        float e = lrelu(g_as1[src * 4 + r] + adv);
        uint2 hv = hp[src * 4 + r];
        float p = __expf(e);
        float2 f01 = __half22float2(*reinterpret_cast<__half2*>(&hv.x));
        float2 f23 = __half22float2(*reinterpret_cast<__half2*>(&hv.y));
        den += p;
        a0 = fmaf(p, f01.x, a0);
        a1 = fmaf(p, f01.y, a1);
        a2 = fmaf(p, f23.x, a2);
        a3 = fmaf(p, f23.y, a3);
        src = nsrc;
    }
#pragma unroll
    for (int o = 4; o < 32; o <<= 1) {
        den += __shfl_xor_sync(0xffffffffu, den, o);
        a0 += __shfl_xor_sync(0xffffffffu, a0, o);
        a1 += __shfl_xor_sync(0xffffffffu, a1, o);
        a2 += __shfl_xor_sync(0xffffffffu, a2, o);
        a3 += __shfl_xor_sync(0xffffffffu, a3, o);
    }
    float inv = 1.f / den;
    float z = 0.f;
    if (lane < 16) {
        int j = lane >> 2;
        float av = (j == 0) ? a0 : (j == 1) ? a1 : (j == 2) ? a2 : a3;
        z = mishf(av * inv + b1[r * 4 + j]);
    }
    float hh = 0.f;
#pragma unroll
    for (int k = 0; k < 16; k++) {
        int c = (k & 3) * 4 + (k >> 2);
        float zk = __shfl_sync(0xffffffffu, z, k);
        hh = fmaf(zk, W2s[c * 32 + lane], hh);
    }
    g_h2h[n * 32 + lane] = __half_raw(__float2half_rn(hh)).x;
    float ss = hh * a_src2[lane];
    float dd = hh * a_dst2[lane];
#pragma unroll
    for (int o = 16; o >= 1; o >>= 1) {
        ss += __shfl_xor_sync(0xffffffffu, ss, o);
        dd += __shfl_xor_sync(0xffffffffu, dd, o);
    }
    if (lane == 0) {
        g_as2[n] = ss;
        g_ad2[n] = dd;
    }
}

// ---------------- Layer 2: warp/node, 8 groups x 4 lanes (8 ch each), half --------
__global__ void l2_edge_kernel(const float* __restrict__ b2) {
    __shared__ float spool[8 * 32];
    __shared__ int sgid[8];
    int tid = threadIdx.x, lane = tid & 31, w = tid >> 5;
    int n = blockIdx.x * 8 + w;
    int g = lane >> 2, r = lane & 3;
    float adv = g_ad2[n];
    int start = g_off[n], end = g_off[n + 1];
    const uint4* hp = reinterpret_cast<const uint4*>(g_h2h);

    float den;
    float ac[8];
    if (g == 0) {  // self loop
        float p = __expf(lrelu(g_as2[n] + adv));
        uint4 hv = hp[n * 4 + r];
        float2 f0 = __half22float2(*reinterpret_cast<__half2*>(&hv.x));
        float2 f1 = __half22float2(*reinterpret_cast<__half2*>(&hv.y));
        float2 f2 = __half22float2(*reinterpret_cast<__half2*>(&hv.z));
        float2 f3 = __half22float2(*reinterpret_cast<__half2*>(&hv.w));
        den = p;
        ac[0] = p * f0.x; ac[1] = p * f0.y; ac[2] = p * f1.x; ac[3] = p * f1.y;
        ac[4] = p * f2.x; ac[5] = p * f2.y; ac[6] = p * f3.x; ac[7] = p * f3.y;
    } else {
        den = 0.f;
#pragma unroll
        for (int c = 0; c < 8; c++) ac[c] = 0.f;
    }
    int idx = start + g;
    int src = (idx < end) ? g_adj[idx] : -1;
    while (src >= 0) {
        idx += 8;
        int nsrc = (idx < end) ? g_adj[idx] : -1;  // prefetch
        float e = lrelu(g_as2[src] + adv);
        uint4 hv = hp[src * 4 + r];
        float p = __expf(e);
        float2 f0 = __half22float2(*reinterpret_cast<__half2*>(&hv.x));
        float2 f1 = __half22float2(*reinterpret_cast<__half2*>(&hv.y));
        float2 f2 = __half22float2(*reinterpret_cast<__half2*>(&hv.z));
        float2 f3 = __half22float2(*reinterpret_cast<__half2*>(&hv.w));
        den += p;
        ac[0] = fmaf(p, f0.x, ac[0]); ac[1] = fmaf(p, f0.y, ac[1]);
        ac[2] = fmaf(p, f1.x, ac[2]); ac[3] = fmaf(p, f1.y, ac[3]);
        ac[4] = fmaf(p, f2.x, ac[4]); ac[5] = fmaf(p, f2.y, ac[5]);
        ac[6] = fmaf(p, f3.x, ac[6]); ac[7] = fmaf(p, f3.y, ac[7]);
        src = nsrc;
    }
#pragma unroll
    for (int o = 4; o < 32; o <<= 1) {
        den += __shfl_xor_sync(0xffffffffu, den, o);
#pragma unroll
        for (int c = 0; c < 8; c++) ac[c] += __shfl_xor_sync(0xffffffffu, ac[c], o);
    }
    if (g == 0) {
        float inv = 1.f / den;
#pragma unroll
        for (int c = 0; c < 8; c++)
            spool[w * 32 + r * 8 + c] = mishf(ac[c] * inv + b2[r * 8 + c]);
        if (lane == 0) sgid[w] = g_batch32[n];
    }
    __syncthreads();
    if (w == 0) {  // block-aggregated pool atomics
        float acc = 0.f;
        int cur = sgid[0];
        for (int row = 0; row < 8; row++) {
            int gid2 = sgid[row];
            if (gid2 != cur) {
                atomicAdd(&g_pool[cur * 32 + lane], acc);
                acc = 0.f;
                cur = gid2;
            }
            acc += spool[row * 32 + lane];
        }
        atomicAdd(&g_pool[cur * 32 + lane], acc);
    }
}

// ---------------- finalize: mean pool ----------------
__global__ void finalize_kernel(float* __restrict__ out) {
    int i = blockIdx.x * 256 + threadIdx.x;
    if (i < NG * 32) out[i] = g_pool[i] / fmaxf(g_cnt[i >> 5], 1.f);
}

extern "C" void kernel_launch(void* const* d_in, const int* in_sizes, int n_in,
                              void* d_out, int out_size) {
    const float* x = (const float*)d_in[0];
    const void* ei = d_in[1];
    const void* bt = d_in[2];
    const float* W1 = (const float*)d_in[3];
    const float* b1 = (const float*)d_in[4];
    const float* a_src1 = (const float*)d_in[5];
    const float* a_dst1 = (const float*)d_in[6];
    const float* W2 = (const float*)d_in[7];
    const float* b2 = (const float*)d_in[8];
    const float* a_src2 = (const float*)d_in[9];
    const float* a_dst2 = (const float*)d_in[10];
    float* out = (float*)d_out;

    zero_detect_kernel<<<(NN + 255) / 256, 256>>>((const int*)ei, (const int*)bt);
    conv_kernel<<<(NE + 255) / 256, 256>>>(ei, bt);
    scan_a_kernel<<<(NN + 1023) / 1024, 1024>>>();
    gemm1_kernel<<<(NN + G1N - 1) / G1N, 128>>>(x, W1, a_src1, a_dst1);
    scan_b_kernel<<<1, 128>>>();
    scan_c_kernel<<<(NN + 255) / 256, 256>>>();
    scatter_kernel<<<(NE + 255) / 256, 256>>>();
    l1_edge_kernel<<<NN / 8, 256>>>(b1, W2, a_src2, a_dst2);
    l2_edge_kernel<<<NN / 8, 256>>>(b2);
    finalize_kernel<<<8, 256>>>(out);
}